// round 7
// baseline (speedup 1.0000x reference)
#include <cuda_runtime.h>
#include <cuda_bf16.h>
#include <cstdint>

// ---------------- problem constants ----------------
#define NODES   262144
#define BGRAPH  1024
#define NPG     256
#define HID     192
#define HID2    384
#define NEDGE   4194304
#define KKEEP   231
#define LN_EPS  1e-5f

// ---------------- head tiling ----------------
#define MTILE   64             // nodes per CTA
#define KSTEPS  12             // K = 192 in chunks of 16
#define NTHREAD 512            // 16 warps: 2 (M) x 8 (N)
// B split global: [kstep 12][split 3][n 384][16 bf16]
#define B_CHUNK_BYTES  36864   // 3*384*16*2
__device__ __align__(16) unsigned char d_Bsplit[12 * B_CHUNK_BYTES];
__device__ float2        d_klg[NODES];      // {keep, logit} packed
__device__ unsigned char d_touched[NODES];

// ---------------- smem layout ----------------
#define A_PITCH   200                    // bf16/row (odd multiple of 8 -> ldsm conflict-free)
#define A_SPLIT_B (MTILE * A_PITCH * 2)  // 25600 B per split
#define OFF_A     0                      // 3 * 25600 = 76800
#define OFF_B     76800                  // 2 * 36864 = 73728 (double buffer)
#define OFF_PAR   150528                 // b1|gamma|beta|w2 : 4*384*4 = 6144
#define OFF_RS1   156672                 // [64][8] floats = 2048
#define OFF_RS2   158720                 // 2048
#define OFF_RT    160768                 // 2048
#define SMEM_REQ  162816

// ---------------- PTX helpers (sm_80-era, safe for compute_103) ----------
__device__ __forceinline__ uint32_t smem_u32(const void* p) {
    uint32_t a;
    asm("{ .reg .u64 t; cvta.to.shared.u64 t, %1; cvt.u32.u64 %0, t; }"
        : "=r"(a) : "l"(p));
    return a;
}
__device__ __forceinline__ void ldsm4(uint32_t* r, uint32_t a) {
    asm volatile("ldmatrix.sync.aligned.m8n8.x4.shared.b16 {%0,%1,%2,%3}, [%4];"
                 : "=r"(r[0]), "=r"(r[1]), "=r"(r[2]), "=r"(r[3]) : "r"(a));
}
__device__ __forceinline__ void ldsm2(uint32_t* r, uint32_t a) {
    asm volatile("ldmatrix.sync.aligned.m8n8.x2.shared.b16 {%0,%1}, [%2];"
                 : "=r"(r[0]), "=r"(r[1]) : "r"(a));
}
__device__ __forceinline__ void mma16816(float* d, const uint32_t* a, const uint32_t* b) {
    asm volatile("mma.sync.aligned.m16n8k16.row.col.f32.bf16.bf16.f32 "
                 "{%0,%1,%2,%3}, {%4,%5,%6,%7}, {%8,%9}, {%0,%1,%2,%3};"
                 : "+f"(d[0]), "+f"(d[1]), "+f"(d[2]), "+f"(d[3])
                 : "r"(a[0]), "r"(a[1]), "r"(a[2]), "r"(a[3]),
                   "r"(b[0]), "r"(b[1]));
}
#define CPASYNC16(dst, src) asm volatile("cp.async.cg.shared.global [%0], [%1], 16;" :: "r"(dst), "l"(src))
#define CPCOMMIT()          asm volatile("cp.async.commit_group;" ::: "memory")
#define CPWAIT(n)           asm volatile("cp.async.wait_group %0;" :: "n"(n) : "memory")

// ---------------------------------------------------------------------------
// Prologue: triple-split W1^T (B[n][k] = W1[k][n]) into k-chunked layout:
//   offset = ks*36864 + s*12288 + n*32 + (k&15)*2
// ---------------------------------------------------------------------------
__global__ void __launch_bounds__(256)
wsplit_kernel(const float* __restrict__ W1)
{
    int idx = blockIdx.x * 256 + threadIdx.x;      // 73728 = 288 * 256
    int n = idx % HID2, k = idx / HID2;
    float x = W1[k * HID2 + n];
    __nv_bfloat16 s1 = __float2bfloat16(x);
    float r1 = x - __bfloat162float(s1);
    __nv_bfloat16 s2 = __float2bfloat16(r1);
    float r2 = r1 - __bfloat162float(s2);
    __nv_bfloat16 s3 = __float2bfloat16(r2);

    uint32_t base = (uint32_t)(k >> 4) * B_CHUNK_BYTES + (uint32_t)n * 32u
                  + (uint32_t)(k & 15) * 2u;
    *(__nv_bfloat16*)(d_Bsplit + base)             = s1;
    *(__nv_bfloat16*)(d_Bsplit + base + 12288)     = s2;
    *(__nv_bfloat16*)(d_Bsplit + base + 24576)     = s3;
}

// no-op launches: align head_kernel to captured launch slot #4 for ncu
__global__ void dummy_kernel() {}

// ---------------------------------------------------------------------------
// Head: 64 nodes x 384 cols per CTA; 16 warps (2 M x 8 N), warp tile 32x48.
// 6-term triple-split bf16 HMMA; b-split-major term order (acc chains 12 apart);
// fused b1 + LayerNorm + ReLU + dot(W2) epilogue.
// ---------------------------------------------------------------------------
__global__ void __launch_bounds__(NTHREAD, 1)
head_kernel(const float* __restrict__ h, const float* __restrict__ g,
            const float* __restrict__ b1, const float* __restrict__ lngamma,
            const float* __restrict__ lnbeta, const float* __restrict__ W2,
            const float* __restrict__ b2, float* __restrict__ logits)
{
    extern __shared__ char sm[];
    const uint32_t sb = smem_u32(sm);

    const int tid  = threadIdx.x;
    const int wid  = tid >> 5;
    const int lane = tid & 31;
    const int wr   = wid & 1;            // M-warp (2)
    const int wc   = wid >> 1;           // N-warp (8), 48 cols each
    const int n0   = blockIdx.x * MTILE;
    const float b2v = __ldg(b2);

    // ---- params -> smem ----
    {
        float* par = (float*)(sm + OFF_PAR);
        if (tid < HID2) {
            par[tid]            = b1[tid];
            par[HID2 + tid]     = lngamma[tid];
            par[2 * HID2 + tid] = lnbeta[tid];
            par[3 * HID2 + tid] = W2[tid];
        }
    }

    // ---- A build: x = h + g[graph], triple split -> smem (pitch 200 bf16) ----
    {
        const float2* h2p = (const float2*)h;
        const int gbase = (n0 >> 8) * HID;
        for (int i = tid; i < MTILE * 96; i += NTHREAD) {   // col-pairs
            int row = i / 96, cp = i % 96;
            float2 hv = h2p[(n0 + row) * 96 + cp];
            int c0 = cp * 2;
            float x0 = hv.x + __ldg(&g[gbase + c0]);
            float x1 = hv.y + __ldg(&g[gbase + c0 + 1]);

            __nv_bfloat16 a0 = __float2bfloat16(x0), e0 = __float2bfloat16(x1);
            float ra = x0 - __bfloat162float(a0), rb = x1 - __bfloat162float(e0);
            __nv_bfloat16 a1 = __float2bfloat16(ra), e1 = __float2bfloat16(rb);
            ra -= __bfloat162float(a1); rb -= __bfloat162float(e1);
            __nv_bfloat16 a2 = __float2bfloat16(ra), e2 = __float2bfloat16(rb);

            uint32_t p0 = ((uint32_t)__bfloat16_as_ushort(e0) << 16) | __bfloat16_as_ushort(a0);
            uint32_t p1 = ((uint32_t)__bfloat16_as_ushort(e1) << 16) | __bfloat16_as_ushort(a1);
            uint32_t p2 = ((uint32_t)__bfloat16_as_ushort(e2) << 16) | __bfloat16_as_ushort(a2);

            uint32_t off = (uint32_t)row * (A_PITCH * 2) + (uint32_t)c0 * 2u;
            *(uint32_t*)(sm + OFF_A + off)                 = p0;
            *(uint32_t*)(sm + OFF_A + A_SPLIT_B + off)     = p1;
            *(uint32_t*)(sm + OFF_A + 2 * A_SPLIT_B + off) = p2;
        }
    }

    // ---- cp.async B chunk 0 into buffer 0 ----
    {
        const char* src = (const char*)d_Bsplit;
        for (int i = tid; i < B_CHUNK_BYTES / 16; i += NTHREAD)
            CPASYNC16(sb + OFF_B + i * 16, src + i * 16);
        CPCOMMIT();
    }

    // ---- ldmatrix addresses ----
    const int q = lane >> 3;
    const uint32_t aRowByte =
        (uint32_t)(wr * 32 + (lane & 7) + ((q & 1) << 3)) * (A_PITCH * 2);
    const uint32_t aColByte = (uint32_t)((q >> 1) << 3) * 2;
    uint32_t aAddr[3][2];
#pragma unroll
    for (int s = 0; s < 3; s++)
#pragma unroll
        for (int m = 0; m < 2; m++)
            aAddr[s][m] = sb + OFF_A + (uint32_t)s * A_SPLIT_B
                        + aRowByte + (uint32_t)m * 16u * (A_PITCH * 2) + aColByte;
    // B .x2: lanes 0-7 -> n rows @k0, lanes 8-15 -> same rows @k0+8
    const uint32_t bLane = (uint32_t)(wc * 48 + (lane & 7)) * 32u
                         + (uint32_t)((lane >> 3) & 1) * 16u;

    float acc[2][6][4];
#pragma unroll
    for (int m = 0; m < 2; m++)
#pragma unroll
        for (int nt = 0; nt < 6; nt++)
#pragma unroll
            for (int j = 0; j < 4; j++) acc[m][nt][j] = 0.f;

    // ---- main loop: 12 k-steps, double-buffered B ----
    for (int ks = 0; ks < KSTEPS; ks++) {
        if (ks + 1 < KSTEPS) {
            const char* src = (const char*)(d_Bsplit + (uint32_t)(ks + 1) * B_CHUNK_BYTES);
            const uint32_t dst = sb + OFF_B + (uint32_t)((ks + 1) & 1) * B_CHUNK_BYTES;
            for (int i = tid; i < B_CHUNK_BYTES / 16; i += NTHREAD)
                CPASYNC16(dst + i * 16, src + i * 16);
            CPCOMMIT();
            CPWAIT(1);
        } else {
            CPWAIT(0);
        }
        __syncthreads();

        const uint32_t kOff = (uint32_t)ks * 32u;
        uint32_t Afr[3][2][4];
#pragma unroll
        for (int s = 0; s < 3; s++)
#pragma unroll
            for (int m = 0; m < 2; m++)
                ldsm4(Afr[s][m], aAddr[s][m] + kOff);

        const uint32_t bBase = sb + OFF_B + (uint32_t)(ks & 1) * B_CHUNK_BYTES + bLane;
        uint32_t Bfr[6][2];

        // b-split 0: terms a1b1, a2b1, a3b1
#pragma unroll
        for (int nt = 0; nt < 6; nt++) ldsm2(Bfr[nt], bBase + (uint32_t)nt * 256u);
#pragma unroll
        for (int sa = 0; sa < 3; sa++)
#pragma unroll
            for (int nt = 0; nt < 6; nt++)
#pragma unroll
                for (int m = 0; m < 2; m++)
                    mma16816(acc[m][nt], Afr[sa][m], Bfr[nt]);

        // b-split 1: terms a1b2, a2b2
#pragma unroll
        for (int nt = 0; nt < 6; nt++) ldsm2(Bfr[nt], bBase + 12288u + (uint32_t)nt * 256u);
#pragma unroll
        for (int sa = 0; sa < 2; sa++)
#pragma unroll
            for (int nt = 0; nt < 6; nt++)
#pragma unroll
                for (int m = 0; m < 2; m++)
                    mma16816(acc[m][nt], Afr[sa][m], Bfr[nt]);

        // b-split 2: term a1b3
#pragma unroll
        for (int nt = 0; nt < 6; nt++) ldsm2(Bfr[nt], bBase + 24576u + (uint32_t)nt * 256u);
#pragma unroll
        for (int nt = 0; nt < 6; nt++)
#pragma unroll
            for (int m = 0; m < 2; m++)
                mma16816(acc[m][nt], Afr[0][m], Bfr[nt]);

        __syncthreads();
    }

    // ---- epilogue: +b1, LN stats, LN+ReLU+dot(W2) ----
    const float* par = (const float*)(sm + OFF_PAR);
    float* rs1 = (float*)(sm + OFF_RS1);
    float* rs2 = (float*)(sm + OFF_RS2);
    float* rt  = (float*)(sm + OFF_RT);
    const int l4 = lane >> 2, lm = lane & 3;

#pragma unroll
    for (int m = 0; m < 2; m++)
#pragma unroll
        for (int hf = 0; hf < 2; hf++) {
            float s1 = 0.f, s2 = 0.f;
#pragma unroll
            for (int nt = 0; nt < 6; nt++) {
                const int cb = wc * 48 + nt * 8 + 2 * lm;
                float2 bv = *(const float2*)&par[cb];
                float v0 = acc[m][nt][2 * hf]     + bv.x;
                float v1 = acc[m][nt][2 * hf + 1] + bv.y;
                s1 += v0 + v1; s2 += v0 * v0 + v1 * v1;
            }
            s1 += __shfl_xor_sync(0xffffffffu, s1, 1);
            s1 += __shfl_xor_sync(0xffffffffu, s1, 2);
            s2 += __shfl_xor_sync(0xffffffffu, s2, 1);
            s2 += __shfl_xor_sync(0xffffffffu, s2, 2);
            if (lm == 0) {
                const int row = wr * 32 + m * 16 + hf * 8 + l4;
                rs1[row * 8 + wc] = s1;
                rs2[row * 8 + wc] = s2;
            }
        }
    __syncthreads();

#pragma unroll
    for (int m = 0; m < 2; m++)
#pragma unroll
        for (int hf = 0; hf < 2; hf++) {
            const int row = wr * 32 + m * 16 + hf * 8 + l4;
            float S1 = 0.f, S2 = 0.f;
#pragma unroll
            for (int j = 0; j < 8; j++) { S1 += rs1[row * 8 + j]; S2 += rs2[row * 8 + j]; }
            const float mu  = S1 * (1.0f / HID2);
            const float var = S2 * (1.0f / HID2) - mu * mu;
            const float inv = rsqrtf(var + LN_EPS);
            float t = 0.f;
#pragma unroll
            for (int nt = 0; nt < 6; nt++) {
                const int cb = wc * 48 + nt * 8 + 2 * lm;
                float2 bv = *(const float2*)&par[cb];
                float2 gm = *(const float2*)&par[HID2 + cb];
                float2 bt = *(const float2*)&par[2 * HID2 + cb];
                float2 w2 = *(const float2*)&par[3 * HID2 + cb];
                float v0 = acc[m][nt][2 * hf]     + bv.x;
                float v1 = acc[m][nt][2 * hf + 1] + bv.y;
                float z0 = fmaxf((v0 - mu) * inv * gm.x + bt.x, 0.f);
                float z1 = fmaxf((v1 - mu) * inv * gm.y + bt.y, 0.f);
                t += z0 * w2.x + z1 * w2.y;
            }
            t += __shfl_xor_sync(0xffffffffu, t, 1);
            t += __shfl_xor_sync(0xffffffffu, t, 2);
            if (lm == 0) rt[row * 8 + wc] = t;
        }
    __syncthreads();
    if (tid < MTILE) {
        float t = b2v;
#pragma unroll
        for (int j = 0; j < 8; j++) t += rt[tid * 8 + j];
        logits[n0 + tid] = t;
    }
}

// ---------------------------------------------------------------------------
// Exact per-graph top-k (jax tie semantics); writes packed {keep, logit};
// zeroes touched[].
// ---------------------------------------------------------------------------
__global__ void __launch_bounds__(256)
topk_kernel(const float* __restrict__ logits)
{
    __shared__ float sv[NPG];
    const int node = blockIdx.x * NPG + threadIdx.x;
    const int t = threadIdx.x;
    const float v = logits[node];
    sv[t] = v;
    d_touched[node] = 0;
    __syncthreads();
    int rank = 0;
#pragma unroll 8
    for (int j = 0; j < NPG; j++) {
        const float u = sv[j];
        rank += (u > v) || (u == v && j < t);
    }
    d_klg[node] = make_float2((rank < KKEEP) ? 1.0f : 0.0f, v);
}

// ---------------------------------------------------------------------------
// Edge masking + weights + touched flags (4 edges / thread, packed gathers)
// ---------------------------------------------------------------------------
__global__ void __launch_bounds__(256)
edge_kernel(const int* __restrict__ ei,
            float* __restrict__ em, float* __restrict__ ew)
{
    const int idx = blockIdx.x * 256 + threadIdx.x;
    const int4 s = ((const int4*)ei)[idx];
    const int4 d = ((const int4*)(ei + NEDGE))[idx];

    const float2 sx = d_klg[s.x], dx = d_klg[d.x];
    const float2 sy = d_klg[s.y], dy = d_klg[d.y];
    const float2 sz = d_klg[s.z], dz = d_klg[d.z];
    const float2 sw = d_klg[s.w], dw = d_klg[d.w];

    float4 m, w;
    m.x = sx.x * dx.x;  w.x = (sx.y + dx.y) * m.x;
    m.y = sy.x * dy.x;  w.y = (sy.y + dy.y) * m.y;
    m.z = sz.x * dz.x;  w.z = (sz.y + dz.y) * m.z;
    m.w = sw.x * dw.x;  w.w = (sw.y + dw.y) * m.w;

    ((float4*)em)[idx] = m;
    ((float4*)ew)[idx] = w;

    if (m.x != 0.f) { d_touched[s.x] = 1; d_touched[d.x] = 1; }
    if (m.y != 0.f) { d_touched[s.y] = 1; d_touched[d.y] = 1; }
    if (m.z != 0.f) { d_touched[s.z] = 1; d_touched[d.z] = 1; }
    if (m.w != 0.f) { d_touched[s.w] = 1; d_touched[d.w] = 1; }
}

__global__ void __launch_bounds__(256)
mask_kernel(float* __restrict__ nm)
{
    const int i = blockIdx.x * 256 + threadIdx.x;
    nm[i] = d_touched[i] ? 1.0f : 0.0f;
}

// ---------------------------------------------------------------------------
// Launch: outputs concatenated f32: edge_mask | edge_weight | logits | node_mask
// head_kernel is launch #4 (ncu capture slot).
// ---------------------------------------------------------------------------
extern "C" void kernel_launch(void* const* d_in, const int* in_sizes, int n_in,
                              void* d_out, int out_size)
{
    const float* h       = (const float*)d_in[0];
    const float* g       = (const float*)d_in[1];
    const int*   ei      = (const int*)  d_in[2];
    const float* W1      = (const float*)d_in[3];
    const float* b1      = (const float*)d_in[4];
    const float* lngamma = (const float*)d_in[5];
    const float* lnbeta  = (const float*)d_in[6];
    const float* W2      = (const float*)d_in[7];
    const float* b2      = (const float*)d_in[8];

    float* out = (float*)d_out;
    float* em = out;
    float* ew = out + (size_t)NEDGE;
    float* lg = out + 2 * (size_t)NEDGE;
    float* nm = lg + NODES;

    cudaFuncSetAttribute(head_kernel,
                         cudaFuncAttributeMaxDynamicSharedMemorySize, SMEM_REQ);

    wsplit_kernel<<<(HID * HID2) / 256, 256>>>(W1);        // #1
    dummy_kernel<<<1, 32>>>();                              // #2
    dummy_kernel<<<1, 32>>>();                              // #3
    head_kernel<<<NODES / MTILE, NTHREAD, SMEM_REQ>>>(      // #4  <- ncu slot
        h, g, b1, lngamma, lnbeta, W2, b2, lg);
    topk_kernel<<<BGRAPH, 256>>>(lg);                       // #5
    edge_kernel<<<NEDGE / 1024, 256>>>(ei, em, ew);         // #6
    mask_kernel<<<NODES / 256, 256>>>(nm);                  // #7
}

// round 8
// speedup vs baseline: 1.9959x; 1.9959x over previous
#include <cuda_runtime.h>
#include <cuda_fp16.h>
#include <cstdint>

// ---------------- problem constants ----------------
#define NODES   262144
#define BGRAPH  1024
#define NPG     256
#define HID     192
#define HID2    384
#define NEDGE   4194304
#define KKEEP   231
#define LN_EPS  1e-5f

// exact power-of-2 scaling keeps all fp16 split terms in normal range
#define XSCALE  256.0f          // A pre-scale (2^8)
#define WSCALE  2048.0f         // B pre-scale (2^11)
#define DESCALE (1.0f / 524288.0f)   // 2^-19

// ---------------- head tiling ----------------
#define MTILE   64             // nodes per CTA
#define KSTEPS  12             // K = 192 in chunks of 16
#define NTHREAD 256            // 8 warps: 2 (M) x 4 (N), warp tile 32 x 96
// B split global: [kstep 12][split 2][n 384][16 fp16]
#define B_CHUNK_BYTES  24576   // 2*384*16*2
__device__ __align__(16) unsigned char d_Bsplit[12 * B_CHUNK_BYTES];
__device__ float2        d_klg[NODES];      // {keep, logit} packed
__device__ unsigned char d_touched[NODES];

// ---------------- smem layout ----------------
#define A_PITCH   200                    // fp16/row (odd multiple of 8 -> ldsm conflict-free)
#define A_SPLIT_B (MTILE * A_PITCH * 2)  // 25600 B per split
#define OFF_A     0                      // 2 * 25600 = 51200
#define OFF_B     51200                  // 2 * 24576 = 49152 (double buffer)
#define OFF_PAR   100352                 // b1|gamma|beta|w2 : 4*384*4 = 6144
#define OFF_RS1   106496                 // [64][4] floats = 1024
#define OFF_RS2   107520                 // 1024
#define OFF_RT    108544                 // 1024
#define SMEM_REQ  109568

// ---------------- PTX helpers (sm_80-era, safe for compute_103) ----------
__device__ __forceinline__ uint32_t smem_u32(const void* p) {
    uint32_t a;
    asm("{ .reg .u64 t; cvta.to.shared.u64 t, %1; cvt.u32.u64 %0, t; }"
        : "=r"(a) : "l"(p));
    return a;
}
__device__ __forceinline__ void ldsm4(uint32_t* r, uint32_t a) {
    asm volatile("ldmatrix.sync.aligned.m8n8.x4.shared.b16 {%0,%1,%2,%3}, [%4];"
                 : "=r"(r[0]), "=r"(r[1]), "=r"(r[2]), "=r"(r[3]) : "r"(a));
}
__device__ __forceinline__ void mma16816(float* d, const uint32_t* a, const uint32_t* b) {
    asm volatile("mma.sync.aligned.m16n8k16.row.col.f32.f16.f16.f32 "
                 "{%0,%1,%2,%3}, {%4,%5,%6,%7}, {%8,%9}, {%0,%1,%2,%3};"
                 : "+f"(d[0]), "+f"(d[1]), "+f"(d[2]), "+f"(d[3])
                 : "r"(a[0]), "r"(a[1]), "r"(a[2]), "r"(a[3]),
                   "r"(b[0]), "r"(b[1]));
}
#define CPASYNC16(dst, src) asm volatile("cp.async.cg.shared.global [%0], [%1], 16;" :: "r"(dst), "l"(src))
#define CPCOMMIT()          asm volatile("cp.async.commit_group;" ::: "memory")
#define CPWAIT(n)           asm volatile("cp.async.wait_group %0;" :: "n"(n) : "memory")

// ---------------------------------------------------------------------------
// Prologue: 2-way fp16 split of W1^T * 2^11 (B[n][k] = W1[k][n] * WSCALE):
//   offset = ks*24576 + s*12288 + n*32 + (k&15)*2
// ---------------------------------------------------------------------------
__global__ void __launch_bounds__(256)
wsplit_kernel(const float* __restrict__ W1)
{
    int idx = blockIdx.x * 256 + threadIdx.x;      // 73728 = 288 * 256
    int n = idx % HID2, k = idx / HID2;
    float x = W1[k * HID2 + n] * WSCALE;
    __half s1 = __float2half_rn(x);
    float r1 = x - __half2float(s1);
    __half s2 = __float2half_rn(r1);

    uint32_t base = (uint32_t)(k >> 4) * B_CHUNK_BYTES + (uint32_t)n * 32u
                  + (uint32_t)(k & 15) * 2u;
    *(__half*)(d_Bsplit + base)         = s1;
    *(__half*)(d_Bsplit + base + 12288) = s2;
}

// no-op launches: keep head_kernel at captured launch slot #4 for ncu
__global__ void dummy_kernel() {}

// ---------------------------------------------------------------------------
// Head: 64 nodes x 384 cols per CTA; 8 warps (2 M x 4 N), warp tile 32x96.
// 4-term fp16 2x2-split HMMA (exact to ~2^-24); b-split-major term order;
// fused b1 + LayerNorm + ReLU + dot(W2) epilogue with 2^-19 descale.
// ---------------------------------------------------------------------------
__global__ void __launch_bounds__(NTHREAD, 1)
head_kernel(const float* __restrict__ h, const float* __restrict__ g,
            const float* __restrict__ b1, const float* __restrict__ lngamma,
            const float* __restrict__ lnbeta, const float* __restrict__ W2,
            const float* __restrict__ b2, float* __restrict__ logits)
{
    extern __shared__ char sm[];
    const uint32_t sb = smem_u32(sm);

    const int tid  = threadIdx.x;
    const int wid  = tid >> 5;
    const int lane = tid & 31;
    const int wr   = wid & 1;            // M-warp (2)
    const int wc   = wid >> 1;           // N-warp (4), 96 cols each
    const int n0   = blockIdx.x * MTILE;
    const float b2v = __ldg(b2);

    // ---- params -> smem ----
    {
        float* par = (float*)(sm + OFF_PAR);
        for (int i = tid; i < HID2; i += NTHREAD) {
            par[i]            = b1[i];
            par[HID2 + i]     = lngamma[i];
            par[2 * HID2 + i] = lnbeta[i];
            par[3 * HID2 + i] = W2[i];
        }
    }

    // ---- A build: x = (h + g[graph]) * 2^8, 2-way fp16 split -> smem ----
    {
        const float2* h2p = (const float2*)h;
        const int gbase = (n0 >> 8) * HID;
        for (int i = tid; i < MTILE * 96; i += NTHREAD) {   // col-pairs
            int row = i / 96, cp = i % 96;
            float2 hv = h2p[(n0 + row) * 96 + cp];
            int c0 = cp * 2;
            float x0 = (hv.x + __ldg(&g[gbase + c0]))     * XSCALE;
            float x1 = (hv.y + __ldg(&g[gbase + c0 + 1])) * XSCALE;

            __half a0 = __float2half_rn(x0), e0 = __float2half_rn(x1);
            float ra = x0 - __half2float(a0), rb = x1 - __half2float(e0);
            __half a1 = __float2half_rn(ra), e1 = __float2half_rn(rb);

            uint32_t p0 = ((uint32_t)__half_as_ushort(e0) << 16) | __half_as_ushort(a0);
            uint32_t p1 = ((uint32_t)__half_as_ushort(e1) << 16) | __half_as_ushort(a1);

            uint32_t off = (uint32_t)row * (A_PITCH * 2) + (uint32_t)c0 * 2u;
            *(uint32_t*)(sm + OFF_A + off)             = p0;
            *(uint32_t*)(sm + OFF_A + A_SPLIT_B + off) = p1;
        }
    }

    // ---- cp.async B chunk 0 into buffer 0 ----
    {
        const char* src = (const char*)d_Bsplit;
        for (int i = tid; i < B_CHUNK_BYTES / 16; i += NTHREAD)
            CPASYNC16(sb + OFF_B + i * 16, src + i * 16);
        CPCOMMIT();
    }

    // ---- ldmatrix addresses ----
    // A .x4 (row-major frag): quad q: rows +(q&1)*8, cols k0 +(q>>1)*8
    const int q = lane >> 3;
    const uint32_t aRowByte =
        (uint32_t)(wr * 32 + (lane & 7) + ((q & 1) << 3)) * (A_PITCH * 2);
    const uint32_t aColByte = (uint32_t)((q >> 1) << 3) * 2;
    uint32_t aAddr[2][2];
#pragma unroll
    for (int s = 0; s < 2; s++)
#pragma unroll
        for (int m = 0; m < 2; m++)
            aAddr[s][m] = sb + OFF_A + (uint32_t)s * A_SPLIT_B
                        + aRowByte + (uint32_t)m * 16u * (A_PITCH * 2) + aColByte;
    // B .x4 covers an nt-pair (16 n-rows x k16):
    //   lanes 0-7: n rows 0-7 @k0 | 8-15: rows 0-7 @k8 | 16-23: rows 8-15 @k0 | 24-31: rows 8-15 @k8
    const uint32_t bRow  = (uint32_t)((lane & 7) + ((lane >> 4) << 3));
    const uint32_t bLane = ((uint32_t)wc * 96u + bRow) * 32u
                         + (uint32_t)((lane >> 3) & 1) * 16u;

    float acc[2][12][4];
#pragma unroll
    for (int m = 0; m < 2; m++)
#pragma unroll
        for (int nt = 0; nt < 12; nt++)
#pragma unroll
            for (int j = 0; j < 4; j++) acc[m][nt][j] = 0.f;

    // ---- main loop: 12 k-steps, double-buffered B ----
    for (int ks = 0; ks < KSTEPS; ks++) {
        __syncthreads();                 // reads of buf[(ks+1)&1] (iter ks-1) done
        if (ks + 1 < KSTEPS) {
            const char* src = (const char*)(d_Bsplit + (uint32_t)(ks + 1) * B_CHUNK_BYTES);
            const uint32_t dst = sb + OFF_B + (uint32_t)((ks + 1) & 1) * B_CHUNK_BYTES;
            for (int i = tid; i < B_CHUNK_BYTES / 16; i += NTHREAD)
                CPASYNC16(dst + i * 16, src + i * 16);
            CPCOMMIT();
            CPWAIT(1);
        } else {
            CPWAIT(0);
        }
        __syncthreads();                 // buf[ks&1] visible to all warps

        const uint32_t kOff = (uint32_t)ks * 32u;
        uint32_t Afr[2][2][4];
#pragma unroll
        for (int s = 0; s < 2; s++)
#pragma unroll
            for (int m = 0; m < 2; m++)
                ldsm4(Afr[s][m], aAddr[s][m] + kOff);

        const uint32_t bBase = sb + OFF_B + (uint32_t)(ks & 1) * B_CHUNK_BYTES + bLane;

#pragma unroll
        for (int sbp = 0; sbp < 2; sbp++) {          // b-split major
            uint32_t Bfr[12][2];
#pragma unroll
            for (int p = 0; p < 6; p++) {            // 6 nt-pairs (96 cols)
                uint32_t r[4];
                ldsm4(r, bBase + (uint32_t)sbp * 12288u + (uint32_t)p * 512u);
                Bfr[2 * p][0] = r[0]; Bfr[2 * p][1] = r[1];
                Bfr[2 * p + 1][0] = r[2]; Bfr[2 * p + 1][1] = r[3];
            }
#pragma unroll
            for (int sa = 0; sa < 2; sa++)           // acc chains 24 apart
#pragma unroll
                for (int nt = 0; nt < 12; nt++)
#pragma unroll
                    for (int m = 0; m < 2; m++)
                        mma16816(acc[m][nt], Afr[sa][m], Bfr[nt]);
        }
    }

    // ---- epilogue: descale, +b1, LN stats, LN+ReLU+dot(W2) ----
    const float* par = (const float*)(sm + OFF_PAR);
    float* rs1 = (float*)(sm + OFF_RS1);
    float* rs2 = (float*)(sm + OFF_RS2);
    float* rt  = (float*)(sm + OFF_RT);
    const int l4 = lane >> 2, lm = lane & 3;

#pragma unroll
    for (int m = 0; m < 2; m++)
#pragma unroll
        for (int hf = 0; hf < 2; hf++) {
            float s1 = 0.f, s2 = 0.f;
#pragma unroll
            for (int nt = 0; nt < 12; nt++) {
                const int cb = wc * 96 + nt * 8 + 2 * lm;
                float2 bv = *(const float2*)&par[cb];
                float v0 = acc[m][nt][2 * hf]     * DESCALE + bv.x;
                float v1 = acc[m][nt][2 * hf + 1] * DESCALE + bv.y;
                s1 += v0 + v1; s2 += v0 * v0 + v1 * v1;
            }
            s1 += __shfl_xor_sync(0xffffffffu, s1, 1);
            s1 += __shfl_xor_sync(0xffffffffu, s1, 2);
            s2 += __shfl_xor_sync(0xffffffffu, s2, 1);
            s2 += __shfl_xor_sync(0xffffffffu, s2, 2);
            if (lm == 0) {
                const int row = wr * 32 + m * 16 + hf * 8 + l4;
                rs1[row * 4 + wc] = s1;
                rs2[row * 4 + wc] = s2;
            }
        }
    __syncthreads();

#pragma unroll
    for (int m = 0; m < 2; m++)
#pragma unroll
        for (int hf = 0; hf < 2; hf++) {
            const int row = wr * 32 + m * 16 + hf * 8 + l4;
            const float S1 = rs1[row * 4] + rs1[row * 4 + 1] + rs1[row * 4 + 2] + rs1[row * 4 + 3];
            const float S2 = rs2[row * 4] + rs2[row * 4 + 1] + rs2[row * 4 + 2] + rs2[row * 4 + 3];
            const float mu  = S1 * (1.0f / HID2);
            const float var = S2 * (1.0f / HID2) - mu * mu;
            const float inv = rsqrtf(var + LN_EPS);
            float t = 0.f;
#pragma unroll
            for (int nt = 0; nt < 12; nt++) {
                const int cb = wc * 96 + nt * 8 + 2 * lm;
                float2 bv = *(const float2*)&par[cb];
                float2 gm = *(const float2*)&par[HID2 + cb];
                float2 bt = *(const float2*)&par[2 * HID2 + cb];
                float2 w2 = *(const float2*)&par[3 * HID2 + cb];
                float v0 = acc[m][nt][2 * hf]     * DESCALE + bv.x;
                float v1 = acc[m][nt][2 * hf + 1] * DESCALE + bv.y;
                float z0 = fmaxf((v0 - mu) * inv * gm.x + bt.x, 0.f);
                float z1 = fmaxf((v1 - mu) * inv * gm.y + bt.y, 0.f);
                t += z0 * w2.x + z1 * w2.y;
            }
            t += __shfl_xor_sync(0xffffffffu, t, 1);
            t += __shfl_xor_sync(0xffffffffu, t, 2);
            if (lm == 0) rt[row * 4 + wc] = t;
        }
    __syncthreads();
    if (tid < MTILE)
        logits[n0 + tid] = rt[tid * 4] + rt[tid * 4 + 1] + rt[tid * 4 + 2]
                         + rt[tid * 4 + 3] + b2v;
}

// ---------------------------------------------------------------------------
// Exact per-graph top-k (jax tie semantics); writes packed {keep, logit};
// zeroes touched[].
// ---------------------------------------------------------------------------
__global__ void __launch_bounds__(256)
topk_kernel(const float* __restrict__ logits)
{
    __shared__ float sv[NPG];
    const int node = blockIdx.x * NPG + threadIdx.x;
    const int t = threadIdx.x;
    const float v = logits[node];
    sv[t] = v;
    d_touched[node] = 0;
    __syncthreads();
    int rank = 0;
#pragma unroll 8
    for (int j = 0; j < NPG; j++) {
        const float u = sv[j];
        rank += (u > v) || (u == v && j < t);
    }
    d_klg[node] = make_float2((rank < KKEEP) ? 1.0f : 0.0f, v);
}

// ---------------------------------------------------------------------------
// Edge masking + weights + touched flags (4 edges / thread, packed gathers)
// ---------------------------------------------------------------------------
__global__ void __launch_bounds__(256)
edge_kernel(const int* __restrict__ ei,
            float* __restrict__ em, float* __restrict__ ew)
{
    const int idx = blockIdx.x * 256 + threadIdx.x;
    const int4 s = ((const int4*)ei)[idx];
    const int4 d = ((const int4*)(ei + NEDGE))[idx];

    const float2 sx = d_klg[s.x], dx = d_klg[d.x];
    const float2 sy = d_klg[s.y], dy = d_klg[d.y];
    const float2 sz = d_klg[s.z], dz = d_klg[d.z];
    const float2 sw = d_klg[s.w], dw = d_klg[d.w];

    float4 m, w;
    m.x = sx.x * dx.x;  w.x = (sx.y + dx.y) * m.x;
    m.y = sy.x * dy.x;  w.y = (sy.y + dy.y) * m.y;
    m.z = sz.x * dz.x;  w.z = (sz.y + dz.y) * m.z;
    m.w = sw.x * dw.x;  w.w = (sw.y + dw.y) * m.w;

    ((float4*)em)[idx] = m;
    ((float4*)ew)[idx] = w;

    if (m.x != 0.f) { d_touched[s.x] = 1; d_touched[d.x] = 1; }
    if (m.y != 0.f) { d_touched[s.y] = 1; d_touched[d.y] = 1; }
    if (m.z != 0.f) { d_touched[s.z] = 1; d_touched[d.z] = 1; }
    if (m.w != 0.f) { d_touched[s.w] = 1; d_touched[d.w] = 1; }
}

__global__ void __launch_bounds__(256)
mask_kernel(float* __restrict__ nm)
{
    const int i = blockIdx.x * 256 + threadIdx.x;
    nm[i] = d_touched[i] ? 1.0f : 0.0f;
}

// ---------------------------------------------------------------------------
// Launch: outputs concatenated f32: edge_mask | edge_weight | logits | node_mask
// head_kernel is launch #4 (ncu capture slot).
// ---------------------------------------------------------------------------
extern "C" void kernel_launch(void* const* d_in, const int* in_sizes, int n_in,
                              void* d_out, int out_size)
{
    const float* h       = (const float*)d_in[0];
    const float* g       = (const float*)d_in[1];
    const int*   ei      = (const int*)  d_in[2];
    const float* W1      = (const float*)d_in[3];
    const float* b1      = (const float*)d_in[4];
    const float* lngamma = (const float*)d_in[5];
    const float* lnbeta  = (const float*)d_in[6];
    const float* W2      = (const float*)d_in[7];
    const float* b2      = (const float*)d_in[8];

    float* out = (float*)d_out;
    float* em = out;
    float* ew = out + (size_t)NEDGE;
    float* lg = out + 2 * (size_t)NEDGE;
    float* nm = lg + NODES;

    cudaFuncSetAttribute(head_kernel,
                         cudaFuncAttributeMaxDynamicSharedMemorySize, SMEM_REQ);

    wsplit_kernel<<<(HID * HID2) / 256, 256>>>(W1);        // #1
    dummy_kernel<<<1, 32>>>();                              // #2
    dummy_kernel<<<1, 32>>>();                              // #3
    head_kernel<<<NODES / MTILE, NTHREAD, SMEM_REQ>>>(      // #4  <- ncu slot
        h, g, b1, lngamma, lnbeta, W2, b2, lg);
    topk_kernel<<<BGRAPH, 256>>>(lg);                       // #5
    edge_kernel<<<NEDGE / 1024, 256>>>(ei, em, ew);         // #6
    mask_kernel<<<NODES / 256, 256>>>(nm);                  // #7
}